// round 12
// baseline (speedup 1.0000x reference)
#include <cuda_runtime.h>
#include <cuda_bf16.h>

#define T_STEPS 512
#define NCTA    96
#define NT      1024

// ---------------- SMEM byte offsets (from 128B-aligned base) ---------------
#define SM_AHI   0                         // 64x512 bf16, swizzled (64KB)
#define SM_ALO   65536                     // 64KB
#define SM_BBUF(bs) (131072 + (bs)*40960)  // 2 bufs x (hi 20480 + lo 20480)
#define SM_HSTG  131072                    // reused in epilogue: 16 x 256 u32
#define SM_BIAS  212992                    // 64 f32
#define SM_WI0   213248                    // 64x8 f32
#define SMEM_ALLOC (215296 + 256)

// ---------------- global scratch -------------------------------------------
__device__ __nv_bfloat16 g_hhi[2][2][256][512];   // [layer][parity][b][k]
__device__ __nv_bfloat16 g_hlo[2][2][256][512];
__device__ float g_Dp[2][32][64][256];            // Wih1 partials, double buffered
__device__ float g_fch[256][256];                 // [row][b]
__device__ unsigned g_arrive = 0;
__device__ unsigned g_gen    = 0;

__device__ __forceinline__ float sigx(float x)  { return 1.0f / (1.0f + __expf(-x)); }
__device__ __forceinline__ float tanhx(float x) { return 2.0f / (1.0f + __expf(-2.0f * x)) - 1.0f; }

__device__ __forceinline__ unsigned smem_u32(const void* p) {
    unsigned a;
    asm("{ .reg .u64 t; cvta.to.shared.u64 t, %1; cvt.u32.u64 %0, t; }" : "=r"(a) : "l"(p));
    return a;
}
__device__ __forceinline__ void ldm_x4(unsigned* r, unsigned addr) {
    asm volatile("ldmatrix.sync.aligned.m8n8.x4.shared.b16 {%0,%1,%2,%3}, [%4];"
        : "=r"(r[0]), "=r"(r[1]), "=r"(r[2]), "=r"(r[3]) : "r"(addr));
}
// B tile is n-major (row = batch column, k contiguous) => NON-trans ldmatrix.
__device__ __forceinline__ void ldm_x2(unsigned* r, unsigned addr) {
    asm volatile("ldmatrix.sync.aligned.m8n8.x2.shared.b16 {%0,%1}, [%2];"
        : "=r"(r[0]), "=r"(r[1]) : "r"(addr));
}
__device__ __forceinline__ void mma16816(float* c, const unsigned* a, const unsigned* b) {
    asm volatile(
        "mma.sync.aligned.m16n8k16.row.col.f32.bf16.bf16.f32 "
        "{%0,%1,%2,%3}, {%4,%5,%6,%7}, {%8,%9}, {%0,%1,%2,%3};"
        : "+f"(c[0]), "+f"(c[1]), "+f"(c[2]), "+f"(c[3])
        : "r"(a[0]), "r"(a[1]), "r"(a[2]), "r"(a[3]), "r"(b[0]), "r"(b[1]));
}
__device__ __forceinline__ void cpasync16(unsigned dst, const void* src) {
    asm volatile("cp.async.cg.shared.global [%0], [%1], 16;" :: "r"(dst), "l"(src));
}

// ---------------- grid barrier (generation counter) ------------------------
__device__ __forceinline__ void grid_barrier() {
    __syncthreads();
    if (threadIdx.x == 0) {
        __threadfence();
        volatile unsigned* genp = &g_gen;
        unsigned snap = *genp;
        unsigned old = atomicAdd(&g_arrive, 1u);
        if (old == (unsigned)(NCTA - 1)) {
            g_arrive = 0u;
            __threadfence();
            atomicAdd(&g_gen, 1u);
        } else {
            while (*genp == snap) { }
        }
        __threadfence();
    }
    __syncthreads();
}

// ---------------------------------------------------------------------------
// Fused 1-barrier-per-tick schedule (32 warps, each owns an 8-wide N-tile):
//  role0 (cta 0..31):  tick t: MMA Whh0*h0[t-1] + fused epilogue -> h0[t]      (t=0..511)
//  role1 (cta 32..63): tick t: MMA Wih1*h0[t-1] -> g_Dp[(t-1)&1]               (t=1..512)
//  role2 (cta 64..95): tick t: MMA Whh1*h1[t-3] + epilogue(+g_Dp[t&1]) -> h1[t-2] (epi t=2..513)
__global__ void __launch_bounds__(NT, 1)
lstm_hmma(const float* __restrict__ u,
          const float* __restrict__ wih0, const float* __restrict__ whh0,
          const float* __restrict__ bih0, const float* __restrict__ bhh0,
          const float* __restrict__ wih1, const float* __restrict__ whh1,
          const float* __restrict__ bih1, const float* __restrict__ bhh1,
          const float* __restrict__ fcw0, const float* __restrict__ fcb0,
          const float* __restrict__ fcw1, const float* __restrict__ fcb1,
          float* __restrict__ out)
{
    extern __shared__ char smraw[];
    char* sm = (char*)((((unsigned long long)(size_t)smraw) + 127) & ~127ULL);
    const unsigned smb = smem_u32(sm);
    const int tid = threadIdx.x, wid = tid >> 5, l = tid & 31;
    const int cta = blockIdx.x;

    const int role = cta >> 5;
    const int m    = cta & 31;          // row-slice: units j0 = m*16
    const float* Asrc = (role == 0) ? whh0 : (role == 1) ? wih1 : whh1;

    // ---- one-time A staging: bf16 hi/lo, row r = g*16+jj, XOR-16B-chunk swizzle
    for (int idx = tid; idx < 64 * 512; idx += NT) {
        int r = idx >> 9, k = idx & 511;
        int grow = (r >> 4) * 512 + m * 16 + (r & 15);
        float w = Asrc[(size_t)grow * 512 + k];
        __nv_bfloat16 hi = __float2bfloat16(w);
        __nv_bfloat16 lo = __float2bfloat16(w - __bfloat162float(hi));
        int chunk = (k >> 3) ^ (r & 7);
        int byte  = r * 1024 + (chunk << 4) + (k & 7) * 2;
        *(__nv_bfloat16*)(sm + SM_AHI + byte) = hi;
        *(__nv_bfloat16*)(sm + SM_ALO + byte) = lo;
    }
    // ---- bias + Wih0 slice (epilogue CTAs: role 0 and 2) ----
    if (role == 0 || role == 2) {
        const float* bi = (role == 2) ? bih1 : bih0;
        const float* bh = (role == 2) ? bhh1 : bhh0;
        if (tid < 64) {
            int grow = (tid >> 4) * 512 + m * 16 + (tid & 15);
            ((float*)(sm + SM_BIAS))[tid] = bi[grow] + bh[grow];
        }
        if (role == 0 && tid < 512) {
            int r = tid >> 3, k = tid & 7;
            int grow = (r >> 4) * 512 + m * 16 + (r & 15);
            ((float*)(sm + SM_WI0))[tid] = wih0[grow * 8 + k];
        }
    }
    __syncthreads();

    // lane-derived ldmatrix address pieces (warp owns 8-wide N-tile = wid)
    const unsigned aRow = (unsigned)((l & 15) * 1024);
    const unsigned aX   = (unsigned)(l & 7);
    const unsigned aK   = (unsigned)(l >> 4);
    const unsigned bN   = (unsigned)((wid * 8 + (l & 7)) * 80);
    const unsigned bK16 = (unsigned)(((l >> 3) & 1) * 16);

    float cst[4];
    #pragma unroll
    for (int i = 0; i < 4; ++i) cst[i] = 0.f;

    float acc[4][4];

    // =================== tick loop (t = 0..513), ONE barrier per tick ======
    #pragma unroll 1
    for (int t = 0; t <= T_STEPS + 1; ++t) {
        bool mma_on = (role == 0) ? (t >= 1 && t <= 511)
                    : (role == 1) ? (t >= 1 && t <= 512)
                                  : (t >= 3);
        if (mma_on) {
            int par = (t - 1) & 1;
            int lay = (role == 2) ? 1 : 0;
            const __nv_bfloat16* hiS = &g_hhi[lay][par][0][0];
            const __nv_bfloat16* loS = &g_hlo[lay][par][0][0];

            #pragma unroll
            for (int g = 0; g < 4; ++g)
                #pragma unroll
                for (int i = 0; i < 4; ++i) acc[g][i] = 0.f;

            // prologue: stage chunk 0 (2048 x 16B over 1024 threads)
            #pragma unroll
            for (int q = 0; q < 2; ++q) {
                int idx = tid + q * NT;
                int part = idx >> 10, r = idx & 1023, n = r >> 2, cc = r & 3;
                const __nv_bfloat16* src = (part ? loS : hiS) + n * 512 + cc * 8;
                cpasync16(smb + SM_BBUF(0) + part * 20480 + n * 80 + cc * 16, src);
            }
            asm volatile("cp.async.commit_group;" ::: "memory");

            #pragma unroll 1
            for (int kc = 0; kc < 16; ++kc) {
                asm volatile("cp.async.wait_group 0;" ::: "memory");
                __syncthreads();                        // buf kc visible everywhere
                if (kc < 15) {                          // issue next into other buffer
                    #pragma unroll
                    for (int q = 0; q < 2; ++q) {
                        int idx = tid + q * NT;
                        int part = idx >> 10, r = idx & 1023, n = r >> 2, cc = r & 3;
                        const __nv_bfloat16* src = (part ? loS : hiS) + n * 512 + (kc + 1) * 32 + cc * 8;
                        cpasync16(smb + SM_BBUF((kc + 1) & 1) + part * 20480 + n * 80 + cc * 16, src);
                    }
                    asm volatile("cp.async.commit_group;" ::: "memory");
                }
                const unsigned bbase = smb + SM_BBUF(kc & 1);
                #pragma unroll
                for (int ks = 0; ks < 2; ++ks) {
                    unsigned bf[2][2];
                    #pragma unroll
                    for (int hl = 0; hl < 2; ++hl)
                        ldm_x2(bf[hl], bbase + hl * 20480 + bN + ks * 32 + bK16);
                    #pragma unroll
                    for (int g = 0; g < 4; ++g) {
                        unsigned ch = (((unsigned)(kc * 4 + ks * 2) + aK) ^ aX) << 4;
                        unsigned ahi[4], alo[4];
                        ldm_x4(ahi, smb + SM_AHI + g * 16384 + aRow + ch);
                        ldm_x4(alo, smb + SM_ALO + g * 16384 + aRow + ch);
                        mma16816(acc[g], ahi, bf[0]);   // Whi*hhi
                        mma16816(acc[g], ahi, bf[1]);   // Whi*hlo
                        mma16816(acc[g], alo, bf[0]);   // Wlo*hhi
                    }
                }
            }
            __syncthreads();   // all MMA reads done before buf area reuse (hstg)

            if (role == 1) {   // store Wih1 partials for role2's next tick
                float* Dp = &g_Dp[(t - 1) & 1][m][0][0];
                #pragma unroll
                for (int g = 0; g < 4; ++g) {
                    int r0 = g * 16 + (l >> 2);
                    int c  = wid * 8 + 2 * (l & 3);
                    float2 v0 = make_float2(acc[g][0], acc[g][1]);
                    float2 v1 = make_float2(acc[g][2], acc[g][3]);
                    __stcg((float2*)(Dp + (size_t)r0 * 256 + c), v0);
                    __stcg((float2*)(Dp + (size_t)(r0 + 8) * 256 + c), v1);
                }
            }
        }

        // -------- fused epilogue (roles 0 and 2) --------
        bool epi_on = (role == 0) ? (t <= 511) : (role == 2) ? (t >= 2) : false;
        if (epi_on) {
            const int step = (role == 0) ? t : t - 2;     // LSTM step index
            const float* BIAS = (const float*)(sm + SM_BIAS);
            const float* WI0  = (const float*)(sm + SM_WI0);
            unsigned* hstg = (unsigned*)(sm + SM_HSTG);
            const bool useacc = mma_on;
            const float* Dp = (role == 2) ? &g_Dp[t & 1][m][0][0] : 0;

            int cb = wid * 8 + 2 * (l & 3);
            float uv[2][8];
            if (role == 0) {
                #pragma unroll
                for (int d = 0; d < 2; ++d) {
                    const float4* up = (const float4*)(u + ((size_t)(cb + d) * T_STEPS + step) * 8);
                    float4 a = __ldg(up), bq = __ldg(up + 1);
                    uv[d][0] = a.x; uv[d][1] = a.y; uv[d][2] = a.z; uv[d][3] = a.w;
                    uv[d][4] = bq.x; uv[d][5] = bq.y; uv[d][6] = bq.z; uv[d][7] = bq.w;
                }
            }
            #pragma unroll
            for (int half = 0; half < 2; ++half) {
                int uu = (l >> 2) + half * 8;
                float pre[4][2];
                #pragma unroll
                for (int g = 0; g < 4; ++g) {
                    float b0 = BIAS[g * 16 + uu];
                    pre[g][0] = b0 + (useacc ? acc[g][half * 2 + 0] : 0.f);
                    pre[g][1] = b0 + (useacc ? acc[g][half * 2 + 1] : 0.f);
                    if (role == 2) {
                        float2 dp = __ldcg((const float2*)(Dp + (size_t)(g * 16 + uu) * 256 + cb));
                        pre[g][0] += dp.x; pre[g][1] += dp.y;
                    }
                    if (role == 0) {
                        const float* wr = WI0 + (g * 16 + uu) * 8;
                        #pragma unroll
                        for (int d = 0; d < 2; ++d) {
                            float s = 0.f;
                            #pragma unroll
                            for (int k = 0; k < 8; ++k) s += wr[k] * uv[d][k];
                            pre[g][d] += s;
                        }
                    }
                }
                #pragma unroll
                for (int d = 0; d < 2; ++d) {
                    int s = half * 2 + d;
                    float ig = sigx(pre[0][d]), fg = sigx(pre[1][d]);
                    float gg = tanhx(pre[2][d]), og = sigx(pre[3][d]);
                    float c = fg * cst[s] + ig * gg;
                    cst[s] = c;
                    float h = og * tanhx(c);
                    __nv_bfloat16 hh = __float2bfloat16(h);
                    __nv_bfloat16 hl2 = __float2bfloat16(h - __bfloat162float(hh));
                    __nv_bfloat162 pk; pk.x = hh; pk.y = hl2;
                    hstg[uu * 256 + cb + d] = *(unsigned*)&pk;
                }
            }
            __syncthreads();
            // coalesced writeback: thread -> (part, b, unit-half), 8 units each
            {
                int part = tid & 1, b = (tid >> 1) & 255, uh = tid >> 9;
                int lay = (role == 0) ? 0 : 1;
                int par = step & 1;
                unsigned o[4];
                #pragma unroll
                for (int i = 0; i < 4; ++i) {
                    unsigned p0 = hstg[(uh * 8 + 2 * i) * 256 + b];
                    unsigned p1 = hstg[(uh * 8 + 2 * i + 1) * 256 + b];
                    unsigned v0 = part ? (p0 >> 16) : (p0 & 0xFFFFu);
                    unsigned v1 = part ? (p1 >> 16) : (p1 & 0xFFFFu);
                    o[i] = v0 | (v1 << 16);
                }
                __nv_bfloat16* dst = (part ? &g_hlo[lay][par][0][0] : &g_hhi[lay][par][0][0])
                                     + (size_t)b * 512 + m * 16 + uh * 8;
                *(uint4*)dst = make_uint4(o[0], o[1], o[2], o[3]);
            }
        }
        grid_barrier();
    }

    // =================== FC head stage A ===================
    for (int cell = cta * NT + tid; cell < 256 * 256; cell += NCTA * NT) {
        int r = cell & 255, b = cell >> 8;
        const float* wrow = fcw0 + (size_t)r * 512;
        const __nv_bfloat16* Hh = &g_hhi[1][1][b][0];   // h1[511], parity 1
        const __nv_bfloat16* Hl = &g_hlo[1][1][b][0];
        float accf = 0.f;
        for (int k = 0; k < 512; k += 8) {
            uint4 vh = __ldcg((const uint4*)(Hh + k));
            uint4 vl = __ldcg((const uint4*)(Hl + k));
            const __nv_bfloat162* ph = (const __nv_bfloat162*)&vh;
            const __nv_bfloat162* pl = (const __nv_bfloat162*)&vl;
            #pragma unroll
            for (int i = 0; i < 4; ++i) {
                float2 a2 = __bfloat1622float2(ph[i]);
                float2 b2 = __bfloat1622float2(pl[i]);
                accf += wrow[k + 2 * i] * (a2.x + b2.x) + wrow[k + 2 * i + 1] * (a2.y + b2.y);
            }
        }
        g_fch[r][b] = tanhf(accf + __ldg(fcb0 + r));
    }
    grid_barrier();

    // =================== FC head stage B ===================
    if (cta == 0 && tid < 256) {
        int b = tid;
        float s0 = __ldg(fcb1 + 0), s1 = __ldg(fcb1 + 1);
        #pragma unroll 8
        for (int k = 0; k < 256; ++k) {
            float v = __ldcg(&g_fch[k][b]);
            s0 += v * __ldg(fcw1 + k);
            s1 += v * __ldg(fcw1 + 256 + k);
        }
        const float scale = 0.5f * (4.2f - 2.5f);
        out[b * 2 + 0] = (s0 + 1.0f) * scale + 2.5f;
        out[b * 2 + 1] = (s1 + 1.0f) * scale + 2.5f;
    }
}

// ---------------------------------------------------------------------------
extern "C" void kernel_launch(void* const* d_in, const int* in_sizes, int n_in,
                              void* d_out, int out_size) {
    (void)in_sizes; (void)n_in; (void)out_size;
    const float* u    = (const float*)d_in[0];
    const float* wih0 = (const float*)d_in[1];
    const float* whh0 = (const float*)d_in[2];
    const float* bih0 = (const float*)d_in[3];
    const float* bhh0 = (const float*)d_in[4];
    const float* wih1 = (const float*)d_in[5];
    const float* whh1 = (const float*)d_in[6];
    const float* bih1 = (const float*)d_in[7];
    const float* bhh1 = (const float*)d_in[8];
    const float* fcw0 = (const float*)d_in[9];
    const float* fcb0 = (const float*)d_in[10];
    const float* fcw1 = (const float*)d_in[11];
    const float* fcb1 = (const float*)d_in[12];
    float* out = (float*)d_out;

    cudaFuncSetAttribute(lstm_hmma,
                         cudaFuncAttributeMaxDynamicSharedMemorySize, SMEM_ALLOC);
    lstm_hmma<<<NCTA, NT, SMEM_ALLOC>>>(
        u, wih0, whh0, bih0, bhh0, wih1, whh1, bih1, bhh1,
        fcw0, fcb0, fcw1, fcb1, out);
}

// round 13
// speedup vs baseline: 1.3812x; 1.3812x over previous
#include <cuda_runtime.h>
#include <cuda_fp16.h>

#define T_STEPS 512
#define NCTA    96
#define NT      512

// ---------------- SMEM byte offsets (from 128B-aligned base) ---------------
#define SM_AHI   0                         // 64x512 fp16 hi, swizzled (64KB)
#define SM_ALO   65536                     // 64KB fp16 lo
#define SM_BBUF(bs) (131072 + (bs)*20480)  // 4 bufs x 20KB (single fp16 h)
#define SM_HSTG  131072                    // reused in epilogue: 16 x 256 u16
#define SM_BIAS  212992                    // 64 f32
#define SM_WI0   213248                    // 64x8 f32
#define SMEM_ALLOC (215296 + 256)

// ---------------- global scratch -------------------------------------------
__device__ __half g_h[2][2][256][512];            // [layer][parity][b][k] fp16
__device__ float g_Dp[2][32][64][256];            // Wih1 partials, double buffered
__device__ float g_fch[256][256];                 // [row][b]
__device__ unsigned g_arrive = 0;
__device__ unsigned g_gen    = 0;

__device__ __forceinline__ float sigx(float x)  { return 1.0f / (1.0f + __expf(-x)); }
__device__ __forceinline__ float tanhx(float x) { return 2.0f / (1.0f + __expf(-2.0f * x)) - 1.0f; }

__device__ __forceinline__ unsigned smem_u32(const void* p) {
    unsigned a;
    asm("{ .reg .u64 t; cvta.to.shared.u64 t, %1; cvt.u32.u64 %0, t; }" : "=r"(a) : "l"(p));
    return a;
}
__device__ __forceinline__ void ldm_x4(unsigned* r, unsigned addr) {
    asm volatile("ldmatrix.sync.aligned.m8n8.x4.shared.b16 {%0,%1,%2,%3}, [%4];"
        : "=r"(r[0]), "=r"(r[1]), "=r"(r[2]), "=r"(r[3]) : "r"(addr));
}
// B tile is n-major (row = batch column, k contiguous) => NON-trans ldmatrix.
__device__ __forceinline__ void ldm_x2(unsigned* r, unsigned addr) {
    asm volatile("ldmatrix.sync.aligned.m8n8.x2.shared.b16 {%0,%1}, [%2];"
        : "=r"(r[0]), "=r"(r[1]) : "r"(addr));
}
__device__ __forceinline__ void mma16816(float* c, const unsigned* a, const unsigned* b) {
    asm volatile(
        "mma.sync.aligned.m16n8k16.row.col.f32.f16.f16.f32 "
        "{%0,%1,%2,%3}, {%4,%5,%6,%7}, {%8,%9}, {%0,%1,%2,%3};"
        : "+f"(c[0]), "+f"(c[1]), "+f"(c[2]), "+f"(c[3])
        : "r"(a[0]), "r"(a[1]), "r"(a[2]), "r"(a[3]), "r"(b[0]), "r"(b[1]));
}
__device__ __forceinline__ void cpasync16(unsigned dst, const void* src) {
    asm volatile("cp.async.cg.shared.global [%0], [%1], 16;" :: "r"(dst), "l"(src));
}

// ---------------- grid barrier (generation counter) ------------------------
__device__ __forceinline__ void grid_barrier() {
    __syncthreads();
    if (threadIdx.x == 0) {
        __threadfence();
        volatile unsigned* genp = &g_gen;
        unsigned snap = *genp;
        unsigned old = atomicAdd(&g_arrive, 1u);
        if (old == (unsigned)(NCTA - 1)) {
            g_arrive = 0u;
            __threadfence();
            atomicAdd(&g_gen, 1u);
        } else {
            while (*genp == snap) { }
        }
        __threadfence();
    }
    __syncthreads();
}

// ---------------------------------------------------------------------------
// Fused 1-barrier-per-tick schedule (16 warps, each owns a 16-wide N-tile):
//  role0 (cta 0..31):  tick t: MMA Whh0*h0[t-1] + fused epilogue -> h0[t]      (t=0..511)
//  role1 (cta 32..63): tick t: MMA Wih1*h0[t-1] -> g_Dp[(t-1)&1]               (t=1..512)
//  role2 (cta 64..95): tick t: MMA Whh1*h1[t-3] + epilogue(+g_Dp[t&1]) -> h1[t-2] (epi t=2..513)
// Precision: W split fp16 hi/lo (2 MMA terms), h stored single fp16.
__global__ void __launch_bounds__(NT, 1)
lstm_hmma(const float* __restrict__ u,
          const float* __restrict__ wih0, const float* __restrict__ whh0,
          const float* __restrict__ bih0, const float* __restrict__ bhh0,
          const float* __restrict__ wih1, const float* __restrict__ whh1,
          const float* __restrict__ bih1, const float* __restrict__ bhh1,
          const float* __restrict__ fcw0, const float* __restrict__ fcb0,
          const float* __restrict__ fcw1, const float* __restrict__ fcb1,
          float* __restrict__ out)
{
    extern __shared__ char smraw[];
    char* sm = (char*)((((unsigned long long)(size_t)smraw) + 127) & ~127ULL);
    const unsigned smb = smem_u32(sm);
    const int tid = threadIdx.x, wid = tid >> 5, l = tid & 31;
    const int cta = blockIdx.x;

    const int role = cta >> 5;
    const int m    = cta & 31;          // row-slice: units j0 = m*16
    const float* Asrc = (role == 0) ? whh0 : (role == 1) ? wih1 : whh1;

    // ---- one-time A staging: fp16 hi/lo, row r = g*16+jj, XOR-16B-chunk swizzle
    for (int idx = tid; idx < 64 * 512; idx += NT) {
        int r = idx >> 9, k = idx & 511;
        int grow = (r >> 4) * 512 + m * 16 + (r & 15);
        float w = Asrc[(size_t)grow * 512 + k];
        __half hi = __float2half_rn(w);
        __half lo = __float2half_rn(w - __half2float(hi));
        int chunk = (k >> 3) ^ (r & 7);
        int byte  = r * 1024 + (chunk << 4) + (k & 7) * 2;
        *(__half*)(sm + SM_AHI + byte) = hi;
        *(__half*)(sm + SM_ALO + byte) = lo;
    }
    // ---- bias + Wih0 slice (epilogue CTAs: role 0 and 2) ----
    if (role == 0 || role == 2) {
        const float* bi = (role == 2) ? bih1 : bih0;
        const float* bh = (role == 2) ? bhh1 : bhh0;
        if (tid < 64) {
            int grow = (tid >> 4) * 512 + m * 16 + (tid & 15);
            ((float*)(sm + SM_BIAS))[tid] = bi[grow] + bh[grow];
        }
        if (role == 0 && tid < 512) {
            int r = tid >> 3, k = tid & 7;
            int grow = (r >> 4) * 512 + m * 16 + (r & 15);
            ((float*)(sm + SM_WI0))[tid] = wih0[grow * 8 + k];
        }
    }
    __syncthreads();

    // lane-derived ldmatrix address pieces (warp owns 16-wide N-tile)
    const unsigned aRow = (unsigned)((l & 15) * 1024);
    const unsigned aX   = (unsigned)(l & 7);
    const unsigned aK   = (unsigned)(l >> 4);
    const unsigned bN   = (unsigned)((wid * 16 + (l & 7)) * 80);
    const unsigned bK16 = (unsigned)(((l >> 3) & 1) * 16);

    float cst[8];
    #pragma unroll
    for (int i = 0; i < 8; ++i) cst[i] = 0.f;

    float acc[4][2][4];

    // =================== tick loop (t = 0..513), ONE barrier per tick ======
    #pragma unroll 1
    for (int t = 0; t <= T_STEPS + 1; ++t) {
        bool mma_on = (role == 0) ? (t >= 1 && t <= 511)
                    : (role == 1) ? (t >= 1 && t <= 512)
                                  : (t >= 3);
        if (mma_on) {
            int par = (t - 1) & 1;
            int lay = (role == 2) ? 1 : 0;
            const __half* hS = &g_h[lay][par][0][0];

            #pragma unroll
            for (int g = 0; g < 4; ++g)
                #pragma unroll
                for (int nt = 0; nt < 2; ++nt)
                    #pragma unroll
                    for (int i = 0; i < 4; ++i) acc[g][nt][i] = 0.f;

            // prologue: stage chunks 0..2 (each 1024 x 16B over 512 threads)
            #pragma unroll
            for (int pc = 0; pc < 3; ++pc) {
                #pragma unroll
                for (int q = 0; q < 2; ++q) {
                    int idx = tid + q * NT;
                    int n = idx >> 2, cc = idx & 3;
                    const __half* src = hS + n * 512 + pc * 32 + cc * 8;
                    cpasync16(smb + SM_BBUF(pc) + n * 80 + cc * 16, src);
                }
                asm volatile("cp.async.commit_group;" ::: "memory");
            }

            #pragma unroll 1
            for (int kc = 0; kc < 16; ++kc) {
                // graduated wait: chunk kc complete, up to 2 chunks in flight
                if (kc <= 13)      asm volatile("cp.async.wait_group 2;" ::: "memory");
                else if (kc == 14) asm volatile("cp.async.wait_group 1;" ::: "memory");
                else               asm volatile("cp.async.wait_group 0;" ::: "memory");
                __syncthreads();                       // buf kc visible; buf (kc+3)&3 free
                if (kc <= 12) {                        // issue chunk kc+3
                    #pragma unroll
                    for (int q = 0; q < 2; ++q) {
                        int idx = tid + q * NT;
                        int n = idx >> 2, cc = idx & 3;
                        const __half* src = hS + n * 512 + (kc + 3) * 32 + cc * 8;
                        cpasync16(smb + SM_BBUF((kc + 3) & 3) + n * 80 + cc * 16, src);
                    }
                    asm volatile("cp.async.commit_group;" ::: "memory");
                }
                const unsigned bbase = smb + SM_BBUF(kc & 3);
                #pragma unroll
                for (int ks = 0; ks < 2; ++ks) {
                    unsigned bf[2][2];
                    #pragma unroll
                    for (int nt = 0; nt < 2; ++nt)
                        ldm_x2(bf[nt], bbase + bN + nt * 640 + ks * 32 + bK16);
                    #pragma unroll
                    for (int g = 0; g < 4; ++g) {
                        unsigned ch = (((unsigned)(kc * 4 + ks * 2) + aK) ^ aX) << 4;
                        unsigned ahi[4], alo[4];
                        ldm_x4(ahi, smb + SM_AHI + g * 16384 + aRow + ch);
                        ldm_x4(alo, smb + SM_ALO + g * 16384 + aRow + ch);
                        #pragma unroll
                        for (int nt = 0; nt < 2; ++nt) {
                            mma16816(acc[g][nt], ahi, bf[nt]);   // Whi*h
                            mma16816(acc[g][nt], alo, bf[nt]);   // Wlo*h
                        }
                    }
                }
            }
            __syncthreads();   // all MMA reads done before buf area reuse (hstg)

            if (role == 1) {   // store Wih1 partials for role2's next tick
                float* Dp = &g_Dp[(t - 1) & 1][m][0][0];
                #pragma unroll
                for (int g = 0; g < 4; ++g)
                    #pragma unroll
                    for (int nt = 0; nt < 2; ++nt) {
                        int r0 = g * 16 + (l >> 2);
                        int c  = wid * 16 + nt * 8 + 2 * (l & 3);
                        float2 v0 = make_float2(acc[g][nt][0], acc[g][nt][1]);
                        float2 v1 = make_float2(acc[g][nt][2], acc[g][nt][3]);
                        __stcg((float2*)(Dp + (size_t)r0 * 256 + c), v0);
                        __stcg((float2*)(Dp + (size_t)(r0 + 8) * 256 + c), v1);
                    }
            }
        }

        // -------- fused epilogue (roles 0 and 2) --------
        bool epi_on = (role == 0) ? (t <= 511) : (role == 2) ? (t >= 2) : false;
        if (epi_on) {
            const int step = (role == 0) ? t : t - 2;     // LSTM step index
            const float* BIAS = (const float*)(sm + SM_BIAS);
            const float* WI0  = (const float*)(sm + SM_WI0);
            unsigned short* hstg = (unsigned short*)(sm + SM_HSTG);
            const bool useacc = mma_on;
            const float* Dp = (role == 2) ? &g_Dp[t & 1][m][0][0] : 0;

            #pragma unroll
            for (int nt = 0; nt < 2; ++nt) {
                int cb = wid * 16 + nt * 8 + 2 * (l & 3);
                float uv[2][8];
                if (role == 0) {
                    #pragma unroll
                    for (int d = 0; d < 2; ++d) {
                        const float4* up = (const float4*)(u + ((size_t)(cb + d) * T_STEPS + step) * 8);
                        float4 a = __ldg(up), bq = __ldg(up + 1);
                        uv[d][0] = a.x; uv[d][1] = a.y; uv[d][2] = a.z; uv[d][3] = a.w;
                        uv[d][4] = bq.x; uv[d][5] = bq.y; uv[d][6] = bq.z; uv[d][7] = bq.w;
                    }
                }
                #pragma unroll
                for (int half = 0; half < 2; ++half) {
                    int uu = (l >> 2) + half * 8;
                    float pre[4][2];
                    #pragma unroll
                    for (int g = 0; g < 4; ++g) {
                        float b0 = BIAS[g * 16 + uu];
                        pre[g][0] = b0 + (useacc ? acc[g][nt][half * 2 + 0] : 0.f);
                        pre[g][1] = b0 + (useacc ? acc[g][nt][half * 2 + 1] : 0.f);
                        if (role == 2) {
                            float2 dp = __ldcg((const float2*)(Dp + (size_t)(g * 16 + uu) * 256 + cb));
                            pre[g][0] += dp.x; pre[g][1] += dp.y;
                        }
                        if (role == 0) {
                            const float* wr = WI0 + (g * 16 + uu) * 8;
                            #pragma unroll
                            for (int d = 0; d < 2; ++d) {
                                float s = 0.f;
                                #pragma unroll
                                for (int k = 0; k < 8; ++k) s += wr[k] * uv[d][k];
                                pre[g][d] += s;
                            }
                        }
                    }
                    #pragma unroll
                    for (int d = 0; d < 2; ++d) {
                        int s = nt * 4 + half * 2 + d;
                        float ig = sigx(pre[0][d]), fg = sigx(pre[1][d]);
                        float gg = tanhx(pre[2][d]), og = sigx(pre[3][d]);
                        float c = fg * cst[s] + ig * gg;
                        cst[s] = c;
                        float h = og * tanhx(c);
                        __half hh = __float2half_rn(h);
                        hstg[uu * 256 + cb + d] = *(unsigned short*)&hh;
                    }
                }
            }
            __syncthreads();
            // coalesced writeback: thread -> (b, unit-half), 8 fp16 = 16B each
            {
                int b = tid & 255, uh = tid >> 8;
                int lay = (role == 0) ? 0 : 1;
                int par = step & 1;
                unsigned o[4];
                #pragma unroll
                for (int i = 0; i < 4; ++i) {
                    unsigned short v0 = hstg[(uh * 8 + 2 * i) * 256 + b];
                    unsigned short v1 = hstg[(uh * 8 + 2 * i + 1) * 256 + b];
                    o[i] = (unsigned)v0 | ((unsigned)v1 << 16);
                }
                __half* dst = &g_h[lay][par][0][0] + (size_t)b * 512 + m * 16 + uh * 8;
                *(uint4*)dst = make_uint4(o[0], o[1], o[2], o[3]);
            }
        }
        grid_barrier();
    }

    // =================== FC head stage A ===================
    for (int cell = cta * NT + tid; cell < 256 * 256; cell += NCTA * NT) {
        int r = cell & 255, b = cell >> 8;
        const float* wrow = fcw0 + (size_t)r * 512;
        const __half* H = &g_h[1][1][b][0];   // h1[511], parity 1
        float accf = 0.f;
        for (int k = 0; k < 512; k += 8) {
            uint4 vh = __ldcg((const uint4*)(H + k));
            const __half2* ph = (const __half2*)&vh;
            #pragma unroll
            for (int i = 0; i < 4; ++i) {
                float2 a2 = __half22float2(ph[i]);
                accf += wrow[k + 2 * i] * a2.x + wrow[k + 2 * i + 1] * a2.y;
            }
        }
        g_fch[r][b] = tanhf(accf + __ldg(fcb0 + r));
    }
    grid_barrier();

    // =================== FC head stage B ===================
    if (cta == 0 && tid < 256) {
        int b = tid;
        float s0 = __ldg(fcb1 + 0), s1 = __ldg(fcb1 + 1);
        #pragma unroll 8
        for (int k = 0; k < 256; ++k) {
            float v = __ldcg(&g_fch[k][b]);
            s0 += v * __ldg(fcw1 + k);
            s1 += v * __ldg(fcw1 + 256 + k);
        }
        const float scale = 0.5f * (4.2f - 2.5f);
        out[b * 2 + 0] = (s0 + 1.0f) * scale + 2.5f;
        out[b * 2 + 1] = (s1 + 1.0f) * scale + 2.5f;
    }
}

// ---------------------------------------------------------------------------
extern "C" void kernel_launch(void* const* d_in, const int* in_sizes, int n_in,
                              void* d_out, int out_size) {
    (void)in_sizes; (void)n_in; (void)out_size;
    const float* u    = (const float*)d_in[0];
    const float* wih0 = (const float*)d_in[1];
    const float* whh0 = (const float*)d_in[2];
    const float* bih0 = (const float*)d_in[3];
    const float* bhh0 = (const float*)d_in[4];
    const float* wih1 = (const float*)d_in[5];
    const float* whh1 = (const float*)d_in[6];
    const float* bih1 = (const float*)d_in[7];
    const float* bhh1 = (const float*)d_in[8];
    const float* fcw0 = (const float*)d_in[9];
    const float* fcb0 = (const float*)d_in[10];
    const float* fcw1 = (const float*)d_in[11];
    const float* fcb1 = (const float*)d_in[12];
    float* out = (float*)d_out;

    cudaFuncSetAttribute(lstm_hmma,
                         cudaFuncAttributeMaxDynamicSharedMemorySize, SMEM_ALLOC);
    lstm_hmma<<<NCTA, NT, SMEM_ALLOC>>>(
        u, wih0, whh0, bih0, bhh0, wih1, whh1, bih1, bhh1,
        fcw0, fcb0, fcw1, fcb1, out);
}

// round 14
// speedup vs baseline: 1.6104x; 1.1660x over previous
#include <cuda_runtime.h>
#include <cuda_fp16.h>

#define T_STEPS 512
#define NCTA    96
#define NT      512

// ---------------- SMEM byte offsets (from 128B-aligned base) ---------------
#define SM_AHI   0                         // 64x512 fp16 hi, swizzled (64KB)
#define SM_ALO   65536                     // 64KB fp16 lo
#define SM_BBUF(bs) (131072 + (bs)*20480)  // 4 bufs x 20KB (warp-private rows)
#define SM_HSTG  131072                    // reused in epilogue: 16 x 256 u16
#define SM_BIAS  212992                    // 64 f32
#define SM_WI0   213248                    // 64x8 f32
#define SMEM_ALLOC (215296 + 256)

// ---------------- global scratch -------------------------------------------
__device__ __half g_h[2][2][256][512];            // [layer][parity][b][k] fp16
__device__ float g_Dp[2][32][64][256];            // Wih1 partials, double buffered
__device__ float g_fch[256][256];                 // [row][b]
__device__ unsigned g_arrive = 0;
__device__ unsigned g_gen    = 0;

__device__ __forceinline__ float sigx(float x)  { return 1.0f / (1.0f + __expf(-x)); }
__device__ __forceinline__ float tanhx(float x) { return 2.0f / (1.0f + __expf(-2.0f * x)) - 1.0f; }

__device__ __forceinline__ unsigned smem_u32(const void* p) {
    unsigned a;
    asm("{ .reg .u64 t; cvta.to.shared.u64 t, %1; cvt.u32.u64 %0, t; }" : "=r"(a) : "l"(p));
    return a;
}
__device__ __forceinline__ void ldm_x4(unsigned* r, unsigned addr) {
    asm volatile("ldmatrix.sync.aligned.m8n8.x4.shared.b16 {%0,%1,%2,%3}, [%4];"
        : "=r"(r[0]), "=r"(r[1]), "=r"(r[2]), "=r"(r[3]) : "r"(addr));
}
// B tile is n-major (row = batch column, k contiguous) => NON-trans ldmatrix.
__device__ __forceinline__ void ldm_x2(unsigned* r, unsigned addr) {
    asm volatile("ldmatrix.sync.aligned.m8n8.x2.shared.b16 {%0,%1}, [%2];"
        : "=r"(r[0]), "=r"(r[1]) : "r"(addr));
}
__device__ __forceinline__ void mma16816(float* c, const unsigned* a, const unsigned* b) {
    asm volatile(
        "mma.sync.aligned.m16n8k16.row.col.f32.f16.f16.f32 "
        "{%0,%1,%2,%3}, {%4,%5,%6,%7}, {%8,%9}, {%0,%1,%2,%3};"
        : "+f"(c[0]), "+f"(c[1]), "+f"(c[2]), "+f"(c[3])
        : "r"(a[0]), "r"(a[1]), "r"(a[2]), "r"(a[3]), "r"(b[0]), "r"(b[1]));
}
__device__ __forceinline__ void cpasync16(unsigned dst, const void* src) {
    asm volatile("cp.async.cg.shared.global [%0], [%1], 16;" :: "r"(dst), "l"(src));
}

// ---------------- grid barrier (generation counter) ------------------------
__device__ __forceinline__ void grid_barrier() {
    __syncthreads();
    if (threadIdx.x == 0) {
        __threadfence();
        volatile unsigned* genp = &g_gen;
        unsigned snap = *genp;
        unsigned old = atomicAdd(&g_arrive, 1u);
        if (old == (unsigned)(NCTA - 1)) {
            g_arrive = 0u;
            __threadfence();
            atomicAdd(&g_gen, 1u);
        } else {
            while (*genp == snap) { }
        }
        __threadfence();
    }
    __syncthreads();
}

// ---------------------------------------------------------------------------
// Fused 1-barrier-per-tick schedule (16 warps, each owns a 16-wide N-tile AND
// stages its own B rows => ZERO __syncthreads in the k-loop):
//  role0 (cta 0..31):  tick t: MMA Whh0*h0[t-1] + fused epilogue -> h0[t]      (t=0..511)
//  role1 (cta 32..63): tick t: MMA Wih1*h0[t-1] -> g_Dp[(t-1)&1]               (t=1..512)
//  role2 (cta 64..95): tick t: MMA Whh1*h1[t-3] + epilogue(+g_Dp[t&1]) -> h1[t-2] (epi t=2..513)
// Precision: W split fp16 hi/lo (2 MMA terms), h stored single fp16.
__global__ void __launch_bounds__(NT, 1)
lstm_hmma(const float* __restrict__ u,
          const float* __restrict__ wih0, const float* __restrict__ whh0,
          const float* __restrict__ bih0, const float* __restrict__ bhh0,
          const float* __restrict__ wih1, const float* __restrict__ whh1,
          const float* __restrict__ bih1, const float* __restrict__ bhh1,
          const float* __restrict__ fcw0, const float* __restrict__ fcb0,
          const float* __restrict__ fcw1, const float* __restrict__ fcb1,
          float* __restrict__ out)
{
    extern __shared__ char smraw[];
    char* sm = (char*)((((unsigned long long)(size_t)smraw) + 127) & ~127ULL);
    const unsigned smb = smem_u32(sm);
    const int tid = threadIdx.x, wid = tid >> 5, l = tid & 31;
    const int cta = blockIdx.x;

    const int role = cta >> 5;
    const int m    = cta & 31;          // row-slice: units j0 = m*16
    const float* Asrc = (role == 0) ? whh0 : (role == 1) ? wih1 : whh1;

    // ---- one-time A staging: fp16 hi/lo, row r = g*16+jj, XOR-16B-chunk swizzle
    for (int idx = tid; idx < 64 * 512; idx += NT) {
        int r = idx >> 9, k = idx & 511;
        int grow = (r >> 4) * 512 + m * 16 + (r & 15);
        float w = Asrc[(size_t)grow * 512 + k];
        __half hi = __float2half_rn(w);
        __half lo = __float2half_rn(w - __half2float(hi));
        int chunk = (k >> 3) ^ (r & 7);
        int byte  = r * 1024 + (chunk << 4) + (k & 7) * 2;
        *(__half*)(sm + SM_AHI + byte) = hi;
        *(__half*)(sm + SM_ALO + byte) = lo;
    }
    // ---- bias + Wih0 slice (epilogue CTAs: role 0 and 2) ----
    if (role == 0 || role == 2) {
        const float* bi = (role == 2) ? bih1 : bih0;
        const float* bh = (role == 2) ? bhh1 : bhh0;
        if (tid < 64) {
            int grow = (tid >> 4) * 512 + m * 16 + (tid & 15);
            ((float*)(sm + SM_BIAS))[tid] = bi[grow] + bh[grow];
        }
        if (role == 0 && tid < 512) {
            int r = tid >> 3, k = tid & 7;
            int grow = (r >> 4) * 512 + m * 16 + (r & 15);
            ((float*)(sm + SM_WI0))[tid] = wih0[grow * 8 + k];
        }
    }
    __syncthreads();

    // lane-derived ldmatrix address pieces (warp owns 16-wide N-tile)
    const unsigned aRow = (unsigned)((l & 15) * 1024);
    const unsigned aX   = (unsigned)(l & 7);
    const unsigned aK   = (unsigned)(l >> 4);
    const unsigned bN   = (unsigned)((wid * 16 + (l & 7)) * 80);
    const unsigned bK16 = (unsigned)(((l >> 3) & 1) * 16);
    // per-warp B staging: lane covers (row, seg) of the warp's 16 rows x 4 segs
    const int sRow = wid * 16 + (l >> 1);       // two (rows x segs) pairs per lane
    const unsigned sDst0 = (unsigned)(sRow * 80);

    float cst[8];
    #pragma unroll
    for (int i = 0; i < 8; ++i) cst[i] = 0.f;

    float acc[4][2][4];

    // =================== tick loop (t = 0..513), ONE barrier per tick ======
    #pragma unroll 1
    for (int t = 0; t <= T_STEPS + 1; ++t) {
        bool mma_on = (role == 0) ? (t >= 1 && t <= 511)
                    : (role == 1) ? (t >= 1 && t <= 512)
                                  : (t >= 3);
        if (mma_on) {
            int par = (t - 1) & 1;
            int lay = (role == 2) ? 1 : 0;
            const __half* hS = &g_h[lay][par][0][0];
            // this lane stages segs (2*(l&1)) and (2*(l&1)+1) of row sRow
            const __half* srcRow = hS + (size_t)sRow * 512;
            const int seg0 = 2 * (l & 1);

            #pragma unroll
            for (int g = 0; g < 4; ++g)
                #pragma unroll
                for (int nt = 0; nt < 2; ++nt)
                    #pragma unroll
                    for (int i = 0; i < 4; ++i) acc[g][nt][i] = 0.f;

            // prologue: stage chunks 0..2 (per-warp own rows, 64x16B per chunk)
            #pragma unroll
            for (int pc = 0; pc < 3; ++pc) {
                #pragma unroll
                for (int q = 0; q < 2; ++q) {
                    int seg = seg0 + q;
                    cpasync16(smb + SM_BBUF(pc) + sDst0 + seg * 16,
                              srcRow + pc * 32 + seg * 8);
                }
                asm volatile("cp.async.commit_group;" ::: "memory");
            }

            #pragma unroll 1
            for (int kc = 0; kc < 16; ++kc) {
                // graduated per-warp wait: chunk kc complete, <=2 in flight
                if (kc <= 13)      asm volatile("cp.async.wait_group 2;" ::: "memory");
                else if (kc == 14) asm volatile("cp.async.wait_group 1;" ::: "memory");
                else               asm volatile("cp.async.wait_group 0;" ::: "memory");
                __syncwarp();                          // warp-local visibility only
                if (kc <= 12) {                        // issue chunk kc+3 (own rows)
                    #pragma unroll
                    for (int q = 0; q < 2; ++q) {
                        int seg = seg0 + q;
                        cpasync16(smb + SM_BBUF((kc + 3) & 3) + sDst0 + seg * 16,
                                  srcRow + (kc + 3) * 32 + seg * 8);
                    }
                    asm volatile("cp.async.commit_group;" ::: "memory");
                }
                const unsigned bbase = smb + SM_BBUF(kc & 3);
                #pragma unroll
                for (int ks = 0; ks < 2; ++ks) {
                    unsigned bf[2][2];
                    #pragma unroll
                    for (int nt = 0; nt < 2; ++nt)
                        ldm_x2(bf[nt], bbase + bN + nt * 640 + ks * 32 + bK16);
                    #pragma unroll
                    for (int g = 0; g < 4; ++g) {
                        unsigned ch = (((unsigned)(kc * 4 + ks * 2) + aK) ^ aX) << 4;
                        unsigned ahi[4], alo[4];
                        ldm_x4(ahi, smb + SM_AHI + g * 16384 + aRow + ch);
                        ldm_x4(alo, smb + SM_ALO + g * 16384 + aRow + ch);
                        #pragma unroll
                        for (int nt = 0; nt < 2; ++nt) {
                            mma16816(acc[g][nt], ahi, bf[nt]);   // Whi*h
                            mma16816(acc[g][nt], alo, bf[nt]);   // Wlo*h
                        }
                    }
                }
            }

            if (role == 1) {   // store Wih1 partials for role2's next tick
                float* Dp = &g_Dp[(t - 1) & 1][m][0][0];
                #pragma unroll
                for (int g = 0; g < 4; ++g)
                    #pragma unroll
                    for (int nt = 0; nt < 2; ++nt) {
                        int r0 = g * 16 + (l >> 2);
                        int c  = wid * 16 + nt * 8 + 2 * (l & 3);
                        float2 v0 = make_float2(acc[g][nt][0], acc[g][nt][1]);
                        float2 v1 = make_float2(acc[g][nt][2], acc[g][nt][3]);
                        __stcg((float2*)(Dp + (size_t)r0 * 256 + c), v0);
                        __stcg((float2*)(Dp + (size_t)(r0 + 8) * 256 + c), v1);
                    }
            }
            __syncthreads();   // ALL warps done with B bufs before hstg aliasing
        }

        // -------- fused epilogue (roles 0 and 2) --------
        bool epi_on = (role == 0) ? (t <= 511) : (role == 2) ? (t >= 2) : false;
        if (epi_on) {
            const int step = (role == 0) ? t : t - 2;     // LSTM step index
            const float* BIAS = (const float*)(sm + SM_BIAS);
            const float* WI0  = (const float*)(sm + SM_WI0);
            unsigned short* hstg = (unsigned short*)(sm + SM_HSTG);
            const bool useacc = mma_on;
            const float* Dp = (role == 2) ? &g_Dp[t & 1][m][0][0] : 0;

            #pragma unroll
            for (int nt = 0; nt < 2; ++nt) {
                int cb = wid * 16 + nt * 8 + 2 * (l & 3);
                float uv[2][8];
                if (role == 0) {
                    #pragma unroll
                    for (int d = 0; d < 2; ++d) {
                        const float4* up = (const float4*)(u + ((size_t)(cb + d) * T_STEPS + step) * 8);
                        float4 a = __ldg(up), bq = __ldg(up + 1);
                        uv[d][0] = a.x; uv[d][1] = a.y; uv[d][2] = a.z; uv[d][3] = a.w;
                        uv[d][4] = bq.x; uv[d][5] = bq.y; uv[d][6] = bq.z; uv[d][7] = bq.w;
                    }
                }
                #pragma unroll
                for (int half = 0; half < 2; ++half) {
                    int uu = (l >> 2) + half * 8;
                    float pre[4][2];
                    #pragma unroll
                    for (int g = 0; g < 4; ++g) {
                        float b0 = BIAS[g * 16 + uu];
                        pre[g][0] = b0 + (useacc ? acc[g][nt][half * 2 + 0] : 0.f);
                        pre[g][1] = b0 + (useacc ? acc[g][nt][half * 2 + 1] : 0.f);
                        if (role == 2) {
                            float2 dp = __ldcg((const float2*)(Dp + (size_t)(g * 16 + uu) * 256 + cb));
                            pre[g][0] += dp.x; pre[g][1] += dp.y;
                        }
                        if (role == 0) {
                            const float* wr = WI0 + (g * 16 + uu) * 8;
                            #pragma unroll
                            for (int d = 0; d < 2; ++d) {
                                float s = 0.f;
                                #pragma unroll
                                for (int k = 0; k < 8; ++k) s += wr[k] * uv[d][k];
                                pre[g][d] += s;
                            }
                        }
                    }
                    #pragma unroll
                    for (int d = 0; d < 2; ++d) {
                        int s = nt * 4 + half * 2 + d;
                        float ig = sigx(pre[0][d]), fg = sigx(pre[1][d]);
                        float gg = tanhx(pre[2][d]), og = sigx(pre[3][d]);
                        float c = fg * cst[s] + ig * gg;
                        cst[s] = c;
                        float h = og * tanhx(c);
                        __half hh = __float2half_rn(h);
                        hstg[uu * 256 + cb + d] = *(unsigned short*)&hh;
                    }
                }
            }
            __syncthreads();
            // coalesced writeback: thread -> (b, unit-half), 8 fp16 = 16B each
            {
                int b = tid & 255, uh = tid >> 8;
                int lay = (role == 0) ? 0 : 1;
                int par = step & 1;
                unsigned o[4];
                #pragma unroll
                for (int i = 0; i < 4; ++i) {
                    unsigned short v0 = hstg[(uh * 8 + 2 * i) * 256 + b];
                    unsigned short v1 = hstg[(uh * 8 + 2 * i + 1) * 256 + b];
                    o[i] = (unsigned)v0 | ((unsigned)v1 << 16);
                }
                __half* dst = &g_h[lay][par][0][0] + (size_t)b * 512 + m * 16 + uh * 8;
                *(uint4*)dst = make_uint4(o[0], o[1], o[2], o[3]);
            }
        }
        grid_barrier();
    }

    // =================== FC head stage A ===================
    for (int cell = cta * NT + tid; cell < 256 * 256; cell += NCTA * NT) {
        int r = cell & 255, b = cell >> 8;
        const float* wrow = fcw0 + (size_t)r * 512;
        const __half* H = &g_h[1][1][b][0];   // h1[511], parity 1
        float accf = 0.f;
        for (int k = 0; k < 512; k += 8) {
            uint4 vh = __ldcg((const uint4*)(H + k));
            const __half2* ph = (const __half2*)&vh;
            #pragma unroll
            for (int i = 0; i < 4; ++i) {
                float2 a2 = __half22float2(ph[i]);
                accf += wrow[k + 2 * i] * a2.x + wrow[k + 2 * i + 1] * a2.y;
            }
        }
        g_fch[r][b] = tanhf(accf + __ldg(fcb0 + r));
    }
    grid_barrier();

    // =================== FC head stage B ===================
    if (cta == 0 && tid < 256) {
        int b = tid;
        float s0 = __ldg(fcb1 + 0), s1 = __ldg(fcb1 + 1);
        #pragma unroll 8
        for (int k = 0; k < 256; ++k) {
            float v = __ldcg(&g_fch[k][b]);
            s0 += v * __ldg(fcw1 + k);
            s1 += v * __ldg(fcw1 + 256 + k);
        }
        const float scale = 0.5f * (4.2f - 2.5f);
        out[b * 2 + 0] = (s0 + 1.0f) * scale + 2.5f;
        out[b * 2 + 1] = (s1 + 1.0f) * scale + 2.5f;
    }
}

// ---------------------------------------------------------------------------
extern "C" void kernel_launch(void* const* d_in, const int* in_sizes, int n_in,
                              void* d_out, int out_size) {
    (void)in_sizes; (void)n_in; (void)out_size;
    const float* u    = (const float*)d_in[0];
    const float* wih0 = (const float*)d_in[1];
    const float* whh0 = (const float*)d_in[2];
    const float* bih0 = (const float*)d_in[3];
    const float* bhh0 = (const float*)d_in[4];
    const float* wih1 = (const float*)d_in[5];
    const float* whh1 = (const float*)d_in[6];
    const float* bih1 = (const float*)d_in[7];
    const float* bhh1 = (const float*)d_in[8];
    const float* fcw0 = (const float*)d_in[9];
    const float* fcb0 = (const float*)d_in[10];
    const float* fcw1 = (const float*)d_in[11];
    const float* fcb1 = (const float*)d_in[12];
    float* out = (float*)d_out;

    cudaFuncSetAttribute(lstm_hmma,
                         cudaFuncAttributeMaxDynamicSharedMemorySize, SMEM_ALLOC);
    lstm_hmma<<<NCTA, NT, SMEM_ALLOC>>>(
        u, wih0, whh0, bih0, bhh0, wih1, whh1, bih1, bhh1,
        fcw0, fcb0, fcw1, fcb1, out);
}

// round 15
// speedup vs baseline: 1.7739x; 1.1015x over previous
#include <cuda_runtime.h>
#include <cuda_fp16.h>

#define T_STEPS 512
#define NCTA    96
#define NT      512

// ---------------- SMEM byte offsets (from 128B-aligned base) ---------------
#define SM_AHI   0                         // 64x512 fp16 hi, swizzled (64KB)
#define SM_ALO   65536                     // 64KB fp16 lo
#define SM_BBUF(bs) (131072 + (bs)*20480)  // 4 bufs x 20KB (warp-private rows)
#define SM_HSTG  131072                    // reused in epilogue: 16 x 256 u16
#define SM_BIAS  212992                    // 64 f32
#define SM_WI0   213248                    // 64x8 f32
#define SMEM_ALLOC (215296 + 256)

// ---------------- global scratch -------------------------------------------
__device__ __half g_h[2][2][256][512];            // [layer][parity][b][k] fp16
__device__ float g_Dp[2][32][64][256];            // Wih1 partials, double buffered
__device__ float g_fch[256][256];                 // [row][b]
__device__ unsigned g_arrive = 0;
__device__ unsigned g_gen    = 0;

// HW tanh (sm_75+): single XU op, no dependent RCP chain.
__device__ __forceinline__ float tanha(float x) {
    float y;
    asm("tanh.approx.f32 %0, %1;" : "=f"(y) : "f"(x));
    return y;
}
__device__ __forceinline__ float sigx(float x)  { return fmaf(tanha(0.5f * x), 0.5f, 0.5f); }

__device__ __forceinline__ unsigned smem_u32(const void* p) {
    unsigned a;
    asm("{ .reg .u64 t; cvta.to.shared.u64 t, %1; cvt.u32.u64 %0, t; }" : "=r"(a) : "l"(p));
    return a;
}
__device__ __forceinline__ void ldm_x4(unsigned* r, unsigned addr) {
    asm volatile("ldmatrix.sync.aligned.m8n8.x4.shared.b16 {%0,%1,%2,%3}, [%4];"
        : "=r"(r[0]), "=r"(r[1]), "=r"(r[2]), "=r"(r[3]) : "r"(addr));
}
// B tile is n-major (row = batch column, k contiguous) => NON-trans ldmatrix.
__device__ __forceinline__ void ldm_x2(unsigned* r, unsigned addr) {
    asm volatile("ldmatrix.sync.aligned.m8n8.x2.shared.b16 {%0,%1}, [%2];"
        : "=r"(r[0]), "=r"(r[1]) : "r"(addr));
}
__device__ __forceinline__ void mma16816(float* c, const unsigned* a, const unsigned* b) {
    asm volatile(
        "mma.sync.aligned.m16n8k16.row.col.f32.f16.f16.f32 "
        "{%0,%1,%2,%3}, {%4,%5,%6,%7}, {%8,%9}, {%0,%1,%2,%3};"
        : "+f"(c[0]), "+f"(c[1]), "+f"(c[2]), "+f"(c[3])
        : "r"(a[0]), "r"(a[1]), "r"(a[2]), "r"(a[3]), "r"(b[0]), "r"(b[1]));
}
__device__ __forceinline__ void cpasync16(unsigned dst, const void* src) {
    asm volatile("cp.async.cg.shared.global [%0], [%1], 16;" :: "r"(dst), "l"(src));
}

// ---------------- grid barrier (generation counter) ------------------------
__device__ __forceinline__ void grid_barrier() {
    __syncthreads();
    if (threadIdx.x == 0) {
        __threadfence();
        volatile unsigned* genp = &g_gen;
        unsigned snap = *genp;
        unsigned old = atomicAdd(&g_arrive, 1u);
        if (old == (unsigned)(NCTA - 1)) {
            g_arrive = 0u;
            __threadfence();
            atomicAdd(&g_gen, 1u);
        } else {
            while (*genp == snap) { }
        }
        __threadfence();
    }
    __syncthreads();
}

// ---------------------------------------------------------------------------
// Fused 1-barrier-per-tick schedule (16 warps, each owns a 16-wide N-tile AND
// stages its own B rows => ZERO __syncthreads in the k-loop):
//  role0 (cta 0..31):  tick t: MMA Whh0*h0[t-1] + fused epilogue -> h0[t]      (t=0..511)
//  role1 (cta 32..63): tick t: MMA Wih1*h0[t-1] -> g_Dp[(t-1)&1]               (t=1..512)
//  role2 (cta 64..95): tick t: MMA Whh1*h1[t-3] + epilogue(+g_Dp[t&1]) -> h1[t-2] (epi t=2..513)
// Precision: W split fp16 hi/lo (2 MMA terms), h stored single fp16.
// Activations: HW tanh.approx (1 XU op each; sigmoid = 0.5*tanh(x/2)+0.5).
__global__ void __launch_bounds__(NT, 1)
lstm_hmma(const float* __restrict__ u,
          const float* __restrict__ wih0, const float* __restrict__ whh0,
          const float* __restrict__ bih0, const float* __restrict__ bhh0,
          const float* __restrict__ wih1, const float* __restrict__ whh1,
          const float* __restrict__ bih1, const float* __restrict__ bhh1,
          const float* __restrict__ fcw0, const float* __restrict__ fcb0,
          const float* __restrict__ fcw1, const float* __restrict__ fcb1,
          float* __restrict__ out)
{
    extern __shared__ char smraw[];
    char* sm = (char*)((((unsigned long long)(size_t)smraw) + 127) & ~127ULL);
    const unsigned smb = smem_u32(sm);
    const int tid = threadIdx.x, wid = tid >> 5, l = tid & 31;
    const int cta = blockIdx.x;

    const int role = cta >> 5;
    const int m    = cta & 31;          // row-slice: units j0 = m*16
    const float* Asrc = (role == 0) ? whh0 : (role == 1) ? wih1 : whh1;

    // ---- one-time A staging: fp16 hi/lo, row r = g*16+jj, XOR-16B-chunk swizzle
    for (int idx = tid; idx < 64 * 512; idx += NT) {
        int r = idx >> 9, k = idx & 511;
        int grow = (r >> 4) * 512 + m * 16 + (r & 15);
        float w = Asrc[(size_t)grow * 512 + k];
        __half hi = __float2half_rn(w);
        __half lo = __float2half_rn(w - __half2float(hi));
        int chunk = (k >> 3) ^ (r & 7);
        int byte  = r * 1024 + (chunk << 4) + (k & 7) * 2;
        *(__half*)(sm + SM_AHI + byte) = hi;
        *(__half*)(sm + SM_ALO + byte) = lo;
    }
    // ---- bias + Wih0 slice (epilogue CTAs: role 0 and 2) ----
    if (role == 0 || role == 2) {
        const float* bi = (role == 2) ? bih1 : bih0;
        const float* bh = (role == 2) ? bhh1 : bhh0;
        if (tid < 64) {
            int grow = (tid >> 4) * 512 + m * 16 + (tid & 15);
            ((float*)(sm + SM_BIAS))[tid] = bi[grow] + bh[grow];
        }
        if (role == 0 && tid < 512) {
            int r = tid >> 3, k = tid & 7;
            int grow = (r >> 4) * 512 + m * 16 + (r & 15);
            ((float*)(sm + SM_WI0))[tid] = wih0[grow * 8 + k];
        }
    }
    __syncthreads();

    // lane-derived ldmatrix address pieces (warp owns 16-wide N-tile)
    const unsigned aRow = (unsigned)((l & 15) * 1024);
    const unsigned aX   = (unsigned)(l & 7);
    const unsigned aK   = (unsigned)(l >> 4);
    const unsigned bN   = (unsigned)((wid * 16 + (l & 7)) * 80);
    const unsigned bK16 = (unsigned)(((l >> 3) & 1) * 16);
    // per-warp B staging: lane covers (row, seg) of the warp's 16 rows x 4 segs
    const int sRow = wid * 16 + (l >> 1);       // two (rows x segs) pairs per lane
    const unsigned sDst0 = (unsigned)(sRow * 80);

    float cst[8];
    #pragma unroll
    for (int i = 0; i < 8; ++i) cst[i] = 0.f;

    float acc[4][2][4];

    // =================== tick loop (t = 0..513), ONE barrier per tick ======
    #pragma unroll 1
    for (int t = 0; t <= T_STEPS + 1; ++t) {
        bool mma_on = (role == 0) ? (t >= 1 && t <= 511)
                    : (role == 1) ? (t >= 1 && t <= 512)
                                  : (t >= 3);
        if (mma_on) {
            int par = (t - 1) & 1;
            int lay = (role == 2) ? 1 : 0;
            const __half* hS = &g_h[lay][par][0][0];
            // this lane stages segs (2*(l&1)) and (2*(l&1)+1) of row sRow
            const __half* srcRow = hS + (size_t)sRow * 512;
            const int seg0 = 2 * (l & 1);

            #pragma unroll
            for (int g = 0; g < 4; ++g)
                #pragma unroll
                for (int nt = 0; nt < 2; ++nt)
                    #pragma unroll
                    for (int i = 0; i < 4; ++i) acc[g][nt][i] = 0.f;

            // prologue: stage chunks 0..2 (per-warp own rows, 64x16B per chunk)
            #pragma unroll
            for (int pc = 0; pc < 3; ++pc) {
                #pragma unroll
                for (int q = 0; q < 2; ++q) {
                    int seg = seg0 + q;
                    cpasync16(smb + SM_BBUF(pc) + sDst0 + seg * 16,
                              srcRow + pc * 32 + seg * 8);
                }
                asm volatile("cp.async.commit_group;" ::: "memory");
            }

            #pragma unroll 1
            for (int kc = 0; kc < 16; ++kc) {
                // graduated per-warp wait: chunk kc complete, <=2 in flight
                if (kc <= 13)      asm volatile("cp.async.wait_group 2;" ::: "memory");
                else if (kc == 14) asm volatile("cp.async.wait_group 1;" ::: "memory");
                else               asm volatile("cp.async.wait_group 0;" ::: "memory");
                __syncwarp();                          // warp-local visibility only
                if (kc <= 12) {                        // issue chunk kc+3 (own rows)
                    #pragma unroll
                    for (int q = 0; q < 2; ++q) {
                        int seg = seg0 + q;
                        cpasync16(smb + SM_BBUF((kc + 3) & 3) + sDst0 + seg * 16,
                                  srcRow + (kc + 3) * 32 + seg * 8);
                    }
                    asm volatile("cp.async.commit_group;" ::: "memory");
                }
                const unsigned bbase = smb + SM_BBUF(kc & 3);
                #pragma unroll
                for (int ks = 0; ks < 2; ++ks) {
                    unsigned bf[2][2];
                    #pragma unroll
                    for (int nt = 0; nt < 2; ++nt)
                        ldm_x2(bf[nt], bbase + bN + nt * 640 + ks * 32 + bK16);
                    #pragma unroll
                    for (int g = 0; g < 4; ++g) {
                        unsigned ch = (((unsigned)(kc * 4 + ks * 2) + aK) ^ aX) << 4;
                        unsigned ahi[4], alo[4];
                        ldm_x4(ahi, smb + SM_AHI + g * 16384 + aRow + ch);
                        ldm_x4(alo, smb + SM_ALO + g * 16384 + aRow + ch);
                        #pragma unroll
                        for (int nt = 0; nt < 2; ++nt) {
                            mma16816(acc[g][nt], ahi, bf[nt]);   // Whi*h
                            mma16816(acc[g][nt], alo, bf[nt]);   // Wlo*h
                        }
                    }
                }
            }

            if (role == 1) {   // store Wih1 partials for role2's next tick
                float* Dp = &g_Dp[(t - 1) & 1][m][0][0];
                #pragma unroll
                for (int g = 0; g < 4; ++g)
                    #pragma unroll
                    for (int nt = 0; nt < 2; ++nt) {
                        int r0 = g * 16 + (l >> 2);
                        int c  = wid * 16 + nt * 8 + 2 * (l & 3);
                        float2 v0 = make_float2(acc[g][nt][0], acc[g][nt][1]);
                        float2 v1 = make_float2(acc[g][nt][2], acc[g][nt][3]);
                        __stcg((float2*)(Dp + (size_t)r0 * 256 + c), v0);
                        __stcg((float2*)(Dp + (size_t)(r0 + 8) * 256 + c), v1);
                    }
            }
            __syncthreads();   // ALL warps done with B bufs before hstg aliasing
        }

        // -------- fused epilogue (roles 0 and 2) --------
        bool epi_on = (role == 0) ? (t <= 511) : (role == 2) ? (t >= 2) : false;
        if (epi_on) {
            const int step = (role == 0) ? t : t - 2;     // LSTM step index
            const float* BIAS = (const float*)(sm + SM_BIAS);
            const float* WI0  = (const float*)(sm + SM_WI0);
            unsigned short* hstg = (unsigned short*)(sm + SM_HSTG);
            const bool useacc = mma_on;
            const float* Dp = (role == 2) ? &g_Dp[t & 1][m][0][0] : 0;

            #pragma unroll
            for (int nt = 0; nt < 2; ++nt) {
                int cb = wid * 16 + nt * 8 + 2 * (l & 3);
                float uv[2][8];
                if (role == 0) {
                    #pragma unroll
                    for (int d = 0; d < 2; ++d) {
                        const float4* up = (const float4*)(u + ((size_t)(cb + d) * T_STEPS + step) * 8);
                        float4 a = __ldg(up), bq = __ldg(up + 1);
                        uv[d][0] = a.x; uv[d][1] = a.y; uv[d][2] = a.z; uv[d][3] = a.w;
                        uv[d][4] = bq.x; uv[d][5] = bq.y; uv[d][6] = bq.z; uv[d][7] = bq.w;
                    }
                }
                #pragma unroll
                for (int half = 0; half < 2; ++half) {
                    int uu = (l >> 2) + half * 8;
                    float pre[4][2];
                    #pragma unroll
                    for (int g = 0; g < 4; ++g) {
                        float b0 = BIAS[g * 16 + uu];
                        pre[g][0] = b0 + (useacc ? acc[g][nt][half * 2 + 0] : 0.f);
                        pre[g][1] = b0 + (useacc ? acc[g][nt][half * 2 + 1] : 0.f);
                        if (role == 2) {
                            float2 dp = __ldcg((const float2*)(Dp + (size_t)(g * 16 + uu) * 256 + cb));
                            pre[g][0] += dp.x; pre[g][1] += dp.y;
                        }
                        if (role == 0) {
                            const float* wr = WI0 + (g * 16 + uu) * 8;
                            #pragma unroll
                            for (int d = 0; d < 2; ++d) {
                                float s = 0.f;
                                #pragma unroll
                                for (int k = 0; k < 8; ++k) s += wr[k] * uv[d][k];
                                pre[g][d] += s;
                            }
                        }
                    }
                    #pragma unroll
                    for (int d = 0; d < 2; ++d) {
                        int s = half * 2 + d + nt * 4;
                        float ig = sigx(pre[0][d]), fg = sigx(pre[1][d]);
                        float gg = tanha(pre[2][d]), og = sigx(pre[3][d]);
                        float c = fg * cst[s] + ig * gg;
                        cst[s] = c;
                        float h = og * tanha(c);
                        __half hh = __float2half_rn(h);
                        hstg[uu * 256 + cb + d] = *(unsigned short*)&hh;
                    }
                }
            }
            __syncthreads();
            // coalesced writeback: thread -> (b, unit-half), 8 fp16 = 16B each
            {
                int b = tid & 255, uh = tid >> 8;
                int lay = (role == 0) ? 0 : 1;
                int par = step & 1;
                unsigned o[4];
                #pragma unroll
                for (int i = 0; i < 4; ++i) {
                    unsigned short v0 = hstg[(uh * 8 + 2 * i) * 256 + b];
                    unsigned short v1 = hstg[(uh * 8 + 2 * i + 1) * 256 + b];
                    o[i] = (unsigned)v0 | ((unsigned)v1 << 16);
                }
                __half* dst = &g_h[lay][par][0][0] + (size_t)b * 512 + m * 16 + uh * 8;
                *(uint4*)dst = make_uint4(o[0], o[1], o[2], o[3]);
            }
        }
        grid_barrier();
    }

    // =================== FC head stage A ===================
    for (int cell = cta * NT + tid; cell < 256 * 256; cell += NCTA * NT) {
        int r = cell & 255, b = cell >> 8;
        const float* wrow = fcw0 + (size_t)r * 512;
        const __half* H = &g_h[1][1][b][0];   // h1[511], parity 1
        float accf = 0.f;
        for (int k = 0; k < 512; k += 8) {
            uint4 vh = __ldcg((const uint4*)(H + k));
            const __half2* ph = (const __half2*)&vh;
            #pragma unroll
            for (int i = 0; i < 4; ++i) {
                float2 a2 = __half22float2(ph[i]);
                accf += wrow[k + 2 * i] * a2.x + wrow[k + 2 * i + 1] * a2.y;
            }
        }
        g_fch[r][b] = tanhf(accf + __ldg(fcb0 + r));
    }
    grid_barrier();

    // =================== FC head stage B ===================
    if (cta == 0 && tid < 256) {
        int b = tid;
        float s0 = __ldg(fcb1 + 0), s1 = __ldg(fcb1 + 1);
        #pragma unroll 8
        for (int k = 0; k < 256; ++k) {
            float v = __ldcg(&g_fch[k][b]);
            s0 += v * __ldg(fcw1 + k);
            s1 += v * __ldg(fcw1 + 256 + k);
        }
        const float scale = 0.5f * (4.2f - 2.5f);
        out[b * 2 + 0] = (s0 + 1.0f) * scale + 2.5f;
        out[b * 2 + 1] = (s1 + 1.0f) * scale + 2.5f;
    }
}

// ---------------------------------------------------------------------------
extern "C" void kernel_launch(void* const* d_in, const int* in_sizes, int n_in,
                              void* d_out, int out_size) {
    (void)in_sizes; (void)n_in; (void)out_size;
    const float* u    = (const float*)d_in[0];
    const float* wih0 = (const float*)d_in[1];
    const float* whh0 = (const float*)d_in[2];
    const float* bih0 = (const float*)d_in[3];
    const float* bhh0 = (const float*)d_in[4];
    const float* wih1 = (const float*)d_in[5];
    const float* whh1 = (const float*)d_in[6];
    const float* bih1 = (const float*)d_in[7];
    const float* bhh1 = (const float*)d_in[8];
    const float* fcw0 = (const float*)d_in[9];
    const float* fcb0 = (const float*)d_in[10];
    const float* fcw1 = (const float*)d_in[11];
    const float* fcb1 = (const float*)d_in[12];
    float* out = (float*)d_out;

    cudaFuncSetAttribute(lstm_hmma,
                         cudaFuncAttributeMaxDynamicSharedMemorySize, SMEM_ALLOC);
    lstm_hmma<<<NCTA, NT, SMEM_ALLOC>>>(
        u, wih0, whh0, bih0, bhh0, wih1, whh1, bih1, bhh1,
        fcw0, fcb0, fcw1, fcb1, out);
}

// round 16
// speedup vs baseline: 2.2904x; 1.2912x over previous
#include <cuda_runtime.h>
#include <cuda_fp16.h>

#define T_STEPS 512
#define NCTA    96
#define NT      512

// ---------------- SMEM byte offsets (from 128B-aligned base) ---------------
#define SM_A     0                         // 64x512 fp16, swizzled (64KB)
#define SM_BBUF(bs) (65536 + (bs)*20480)   // 4 bufs x 20KB (warp-private rows)
#define SM_HSTG  65536                     // reused in epilogue: 16 x 256 u16
#define SM_BIAS  147456                    // 64 f32
#define SM_WI0   147712                    // 64x8 f32
#define SMEM_ALLOC (149760 + 256)

// ---------------- global scratch -------------------------------------------
__device__ __half g_h[2][2][256][512];            // [layer][parity][b][k] fp16
__device__ float g_Dp[2][32][64][256];            // Wih1 partials, double buffered
__device__ float g_fch[256][256];                 // [row][b]
__device__ unsigned g_arrive = 0;
__device__ unsigned g_gen    = 0;

// HW tanh (sm_75+): single XU op, no dependent RCP chain.
__device__ __forceinline__ float tanha(float x) {
    float y;
    asm("tanh.approx.f32 %0, %1;" : "=f"(y) : "f"(x));
    return y;
}
__device__ __forceinline__ float sigx(float x)  { return fmaf(tanha(0.5f * x), 0.5f, 0.5f); }

__device__ __forceinline__ unsigned smem_u32(const void* p) {
    unsigned a;
    asm("{ .reg .u64 t; cvta.to.shared.u64 t, %1; cvt.u32.u64 %0, t; }" : "=r"(a) : "l"(p));
    return a;
}
__device__ __forceinline__ void ldm_x4(unsigned* r, unsigned addr) {
    asm volatile("ldmatrix.sync.aligned.m8n8.x4.shared.b16 {%0,%1,%2,%3}, [%4];"
        : "=r"(r[0]), "=r"(r[1]), "=r"(r[2]), "=r"(r[3]) : "r"(addr));
}
// B tile is n-major (row = batch column, k contiguous) => NON-trans ldmatrix.
__device__ __forceinline__ void ldm_x2(unsigned* r, unsigned addr) {
    asm volatile("ldmatrix.sync.aligned.m8n8.x2.shared.b16 {%0,%1}, [%2];"
        : "=r"(r[0]), "=r"(r[1]) : "r"(addr));
}
__device__ __forceinline__ void mma16816(float* c, const unsigned* a, const unsigned* b) {
    asm volatile(
        "mma.sync.aligned.m16n8k16.row.col.f32.f16.f16.f32 "
        "{%0,%1,%2,%3}, {%4,%5,%6,%7}, {%8,%9}, {%0,%1,%2,%3};"
        : "+f"(c[0]), "+f"(c[1]), "+f"(c[2]), "+f"(c[3])
        : "r"(a[0]), "r"(a[1]), "r"(a[2]), "r"(a[3]), "r"(b[0]), "r"(b[1]));
}
__device__ __forceinline__ void cpasync16(unsigned dst, const void* src) {
    asm volatile("cp.async.cg.shared.global [%0], [%1], 16;" :: "r"(dst), "l"(src));
}

// ---------------- grid barrier (generation counter) ------------------------
__device__ __forceinline__ void grid_barrier() {
    __syncthreads();
    if (threadIdx.x == 0) {
        __threadfence();
        volatile unsigned* genp = &g_gen;
        unsigned snap = *genp;
        unsigned old = atomicAdd(&g_arrive, 1u);
        if (old == (unsigned)(NCTA - 1)) {
            g_arrive = 0u;
            __threadfence();
            atomicAdd(&g_gen, 1u);
        } else {
            while (*genp == snap) { }
        }
        __threadfence();
    }
    __syncthreads();
}

// ---------------------------------------------------------------------------
// Fused 1-barrier-per-tick schedule (16 warps, each owns a 16-wide N-tile AND
// stages its own B rows => ZERO __syncthreads in the k-loop):
//  role0 (cta 0..31):  tick t: MMA Whh0*h0[t-1] + fused epilogue -> h0[t]      (t=0..511)
//  role1 (cta 32..63): tick t: MMA Wih1*h0[t-1] -> g_Dp[(t-1)&1]               (t=1..512)
//  role2 (cta 64..95): tick t: MMA Whh1*h1[t-3] + epilogue(+g_Dp[t&1]) -> h1[t-2] (epi t=2..513)
// Precision: W single fp16 (same error scale as the existing fp16-h storage),
// h stored single fp16. Activations: HW tanh.approx.
__global__ void __launch_bounds__(NT, 1)
lstm_hmma(const float* __restrict__ u,
          const float* __restrict__ wih0, const float* __restrict__ whh0,
          const float* __restrict__ bih0, const float* __restrict__ bhh0,
          const float* __restrict__ wih1, const float* __restrict__ whh1,
          const float* __restrict__ bih1, const float* __restrict__ bhh1,
          const float* __restrict__ fcw0, const float* __restrict__ fcb0,
          const float* __restrict__ fcw1, const float* __restrict__ fcb1,
          float* __restrict__ out)
{
    extern __shared__ char smraw[];
    char* sm = (char*)((((unsigned long long)(size_t)smraw) + 127) & ~127ULL);
    const unsigned smb = smem_u32(sm);
    const int tid = threadIdx.x, wid = tid >> 5, l = tid & 31;
    const int cta = blockIdx.x;

    const int role = cta >> 5;
    const int m    = cta & 31;          // row-slice: units j0 = m*16
    const float* Asrc = (role == 0) ? whh0 : (role == 1) ? wih1 : whh1;

    // ---- one-time A staging: single fp16, row r = g*16+jj, XOR-16B-chunk swizzle
    for (int idx = tid; idx < 64 * 512; idx += NT) {
        int r = idx >> 9, k = idx & 511;
        int grow = (r >> 4) * 512 + m * 16 + (r & 15);
        float w = Asrc[(size_t)grow * 512 + k];
        int chunk = (k >> 3) ^ (r & 7);
        int byte  = r * 1024 + (chunk << 4) + (k & 7) * 2;
        *(__half*)(sm + SM_A + byte) = __float2half_rn(w);
    }
    // ---- bias + Wih0 slice (epilogue CTAs: role 0 and 2) ----
    if (role == 0 || role == 2) {
        const float* bi = (role == 2) ? bih1 : bih0;
        const float* bh = (role == 2) ? bhh1 : bhh0;
        if (tid < 64) {
            int grow = (tid >> 4) * 512 + m * 16 + (tid & 15);
            ((float*)(sm + SM_BIAS))[tid] = bi[grow] + bh[grow];
        }
        if (role == 0 && tid < 512) {
            int r = tid >> 3, k = tid & 7;
            int grow = (r >> 4) * 512 + m * 16 + (r & 15);
            ((float*)(sm + SM_WI0))[tid] = wih0[grow * 8 + k];
        }
    }
    __syncthreads();

    // lane-derived ldmatrix address pieces (warp owns 16-wide N-tile)
    const unsigned aRow = (unsigned)((l & 15) * 1024);
    const unsigned aX   = (unsigned)(l & 7);
    const unsigned aK   = (unsigned)(l >> 4);
    const unsigned bN   = (unsigned)((wid * 16 + (l & 7)) * 80);
    const unsigned bK16 = (unsigned)(((l >> 3) & 1) * 16);
    // per-warp B staging: lane covers (row, seg) of the warp's 16 rows x 4 segs
    const int sRow = wid * 16 + (l >> 1);       // two (rows x segs) pairs per lane
    const unsigned sDst0 = (unsigned)(sRow * 80);

    float cst[8];
    #pragma unroll
    for (int i = 0; i < 8; ++i) cst[i] = 0.f;

    float acc[4][2][4];

    // =================== tick loop (t = 0..513), ONE barrier per tick ======
    #pragma unroll 1
    for (int t = 0; t <= T_STEPS + 1; ++t) {
        bool mma_on = (role == 0) ? (t >= 1 && t <= 511)
                    : (role == 1) ? (t >= 1 && t <= 512)
                                  : (t >= 3);
        if (mma_on) {
            int par = (t - 1) & 1;
            int lay = (role == 2) ? 1 : 0;
            const __half* hS = &g_h[lay][par][0][0];
            // this lane stages segs (2*(l&1)) and (2*(l&1)+1) of row sRow
            const __half* srcRow = hS + (size_t)sRow * 512;
            const int seg0 = 2 * (l & 1);

            #pragma unroll
            for (int g = 0; g < 4; ++g)
                #pragma unroll
                for (int nt = 0; nt < 2; ++nt)
                    #pragma unroll
                    for (int i = 0; i < 4; ++i) acc[g][nt][i] = 0.f;

            // prologue: stage chunks 0..2 (per-warp own rows, 64x16B per chunk)
            #pragma unroll
            for (int pc = 0; pc < 3; ++pc) {
                #pragma unroll
                for (int q = 0; q < 2; ++q) {
                    int seg = seg0 + q;
                    cpasync16(smb + SM_BBUF(pc) + sDst0 + seg * 16,
                              srcRow + pc * 32 + seg * 8);
                }
                asm volatile("cp.async.commit_group;" ::: "memory");
            }

            #pragma unroll 1
            for (int kc = 0; kc < 16; ++kc) {
                // graduated per-warp wait: chunk kc complete, <=2 in flight
                if (kc <= 13)      asm volatile("cp.async.wait_group 2;" ::: "memory");
                else if (kc == 14) asm volatile("cp.async.wait_group 1;" ::: "memory");
                else               asm volatile("cp.async.wait_group 0;" ::: "memory");
                __syncwarp();                          // warp-local visibility only
                if (kc <= 12) {                        // issue chunk kc+3 (own rows)
                    #pragma unroll
                    for (int q = 0; q < 2; ++q) {
                        int seg = seg0 + q;
                        cpasync16(smb + SM_BBUF((kc + 3) & 3) + sDst0 + seg * 16,
                                  srcRow + (kc + 3) * 32 + seg * 8);
                    }
                    asm volatile("cp.async.commit_group;" ::: "memory");
                }
                const unsigned bbase = smb + SM_BBUF(kc & 3);
                #pragma unroll
                for (int ks = 0; ks < 2; ++ks) {
                    unsigned bf[2][2];
                    #pragma unroll
                    for (int nt = 0; nt < 2; ++nt)
                        ldm_x2(bf[nt], bbase + bN + nt * 640 + ks * 32 + bK16);
                    #pragma unroll
                    for (int g = 0; g < 4; ++g) {
                        unsigned ch = (((unsigned)(kc * 4 + ks * 2) + aK) ^ aX) << 4;
                        unsigned af[4];
                        ldm_x4(af, smb + SM_A + g * 16384 + aRow + ch);
                        #pragma unroll
                        for (int nt = 0; nt < 2; ++nt)
                            mma16816(acc[g][nt], af, bf[nt]);   // W*h (single term)
                    }
                }
            }

            if (role == 1) {   // store Wih1 partials for role2's next tick
                float* Dp = &g_Dp[(t - 1) & 1][m][0][0];
                #pragma unroll
                for (int g = 0; g < 4; ++g)
                    #pragma unroll
                    for (int nt = 0; nt < 2; ++nt) {
                        int r0 = g * 16 + (l >> 2);
                        int c  = wid * 16 + nt * 8 + 2 * (l & 3);
                        float2 v0 = make_float2(acc[g][nt][0], acc[g][nt][1]);
                        float2 v1 = make_float2(acc[g][nt][2], acc[g][nt][3]);
                        __stcg((float2*)(Dp + (size_t)r0 * 256 + c), v0);
                        __stcg((float2*)(Dp + (size_t)(r0 + 8) * 256 + c), v1);
                    }
            }
            __syncthreads();   // ALL warps done with B bufs before hstg aliasing
        }

        // -------- fused epilogue (roles 0 and 2) --------
        bool epi_on = (role == 0) ? (t <= 511) : (role == 2) ? (t >= 2) : false;
        if (epi_on) {
            const int step = (role == 0) ? t : t - 2;     // LSTM step index
            const float* BIAS = (const float*)(sm + SM_BIAS);
            const float* WI0  = (const float*)(sm + SM_WI0);
            unsigned short* hstg = (unsigned short*)(sm + SM_HSTG);
            const bool useacc = mma_on;
            const float* Dp = (role == 2) ? &g_Dp[t & 1][m][0][0] : 0;

            #pragma unroll
            for (int nt = 0; nt < 2; ++nt) {
                int cb = wid * 16 + nt * 8 + 2 * (l & 3);
                float uv[2][8];
                if (role == 0) {
                    #pragma unroll
                    for (int d = 0; d < 2; ++d) {
                        const float4* up = (const float4*)(u + ((size_t)(cb + d) * T_STEPS + step) * 8);
                        float4 a = __ldg(up), bq = __ldg(up + 1);
                        uv[d][0] = a.x; uv[d][1] = a.y; uv[d][2] = a.z; uv[d][3] = a.w;
                        uv[d][4] = bq.x; uv[d][5] = bq.y; uv[d][6] = bq.z; uv[d][7] = bq.w;
                    }
                }
                #pragma unroll
                for (int half = 0; half < 2; ++half) {
                    int uu = (l >> 2) + half * 8;
                    float pre[4][2];
                    #pragma unroll
                    for (int g = 0; g < 4; ++g) {
                        float b0 = BIAS[g * 16 + uu];
                        pre[g][0] = b0 + (useacc ? acc[g][nt][half * 2 + 0] : 0.f);
                        pre[g][1] = b0 + (useacc ? acc[g][nt][half * 2 + 1] : 0.f);
                        if (role == 2) {
                            float2 dp = __ldcg((const float2*)(Dp + (size_t)(g * 16 + uu) * 256 + cb));
                            pre[g][0] += dp.x; pre[g][1] += dp.y;
                        }
                        if (role == 0) {
                            const float* wr = WI0 + (g * 16 + uu) * 8;
                            #pragma unroll
                            for (int d = 0; d < 2; ++d) {
                                float s = 0.f;
                                #pragma unroll
                                for (int k = 0; k < 8; ++k) s += wr[k] * uv[d][k];
                                pre[g][d] += s;
                            }
                        }
                    }
                    #pragma unroll
                    for (int d = 0; d < 2; ++d) {
                        int s = half * 2 + d + nt * 4;
                        float ig = sigx(pre[0][d]), fg = sigx(pre[1][d]);
                        float gg = tanha(pre[2][d]), og = sigx(pre[3][d]);
                        float c = fg * cst[s] + ig * gg;
                        cst[s] = c;
                        float h = og * tanha(c);
                        __half hh = __float2half_rn(h);
                        hstg[uu * 256 + cb + d] = *(unsigned short*)&hh;
                    }
                }
            }
            __syncthreads();
            // coalesced writeback: thread -> (b, unit-half), 8 fp16 = 16B each
            {
                int b = tid & 255, uh = tid >> 8;
                int lay = (role == 0) ? 0 : 1;
                int par = step & 1;
                unsigned o[4];
                #pragma unroll
                for (int i = 0; i < 4; ++i) {
                    unsigned short v0 = hstg[(uh * 8 + 2 * i) * 256 + b];
                    unsigned short v1 = hstg[(uh * 8 + 2 * i + 1) * 256 + b];
                    o[i] = (unsigned)v0 | ((unsigned)v1 << 16);
                }
                __half* dst = &g_h[lay][par][0][0] + (size_t)b * 512 + m * 16 + uh * 8;
                *(uint4*)dst = make_uint4(o[0], o[1], o[2], o[3]);
            }
        }
        grid_barrier();
    }

    // =================== FC head stage A ===================
    for (int cell = cta * NT + tid; cell < 256 * 256; cell += NCTA * NT) {
        int r = cell & 255, b = cell >> 8;
        const float* wrow = fcw0 + (size_t)r * 512;
        const __half* H = &g_h[1][1][b][0];   // h1[511], parity 1
        float accf = 0.f;
        for (int k = 0; k < 512; k += 8) {
            uint4 vh = __ldcg((const uint4*)(H + k));
            const __half2* ph = (const __half2*)&vh;
            #pragma unroll
            for (int i = 0; i < 4; ++i) {
                float2 a2 = __half22float2(ph[i]);
                accf += wrow[k + 2 * i] * a2.x + wrow[k + 2 * i + 1] * a2.y;
            }
        }
        g_fch[r][b] = tanhf(accf + __ldg(fcb0 + r));
    }
    grid_barrier();

    // =================== FC head stage B ===================
    if (cta == 0 && tid < 256) {
        int b = tid;
        float s0 = __ldg(fcb1 + 0), s1 = __ldg(fcb1 + 1);
        #pragma unroll 8
        for (int k = 0; k < 256; ++k) {
            float v = __ldcg(&g_fch[k][b]);
            s0 += v * __ldg(fcw1 + k);
            s1 += v * __ldg(fcw1 + 256 + k);
        }
        const float scale = 0.5f * (4.2f - 2.5f);
        out[b * 2 + 0] = (s0 + 1.0f) * scale + 2.5f;
        out[b * 2 + 1] = (s1 + 1.0f) * scale + 2.5f;
    }
}

// ---------------------------------------------------------------------------
extern "C" void kernel_launch(void* const* d_in, const int* in_sizes, int n_in,
                              void* d_out, int out_size) {
    (void)in_sizes; (void)n_in; (void)out_size;
    const float* u    = (const float*)d_in[0];
    const float* wih0 = (const float*)d_in[1];
    const float* whh0 = (const float*)d_in[2];
    const float* bih0 = (const float*)d_in[3];
    const float* bhh0 = (const float*)d_in[4];
    const float* wih1 = (const float*)d_in[5];
    const float* whh1 = (const float*)d_in[6];
    const float* bih1 = (const float*)d_in[7];
    const float* bhh1 = (const float*)d_in[8];
    const float* fcw0 = (const float*)d_in[9];
    const float* fcb0 = (const float*)d_in[10];
    const float* fcw1 = (const float*)d_in[11];
    const float* fcb1 = (const float*)d_in[12];
    float* out = (float*)d_out;

    cudaFuncSetAttribute(lstm_hmma,
                         cudaFuncAttributeMaxDynamicSharedMemorySize, SMEM_ALLOC);
    lstm_hmma<<<NCTA, NT, SMEM_ALLOC>>>(
        u, wih0, whh0, bih0, bhh0, wih1, whh1, bih1, bhh1,
        fcw0, fcb0, fcw1, fcb1, out);
}